// round 8
// baseline (speedup 1.0000x reference)
#include <cuda_runtime.h>
#include <cuda_bf16.h>
#include <cstdint>

// Problem constants (fixed shapes)
#define B_SZ   256
#define T_SZ   512
#define EMB    128
#define HID    256
#define NCLS   32000

// Scratch: h0 at last timestep, stored bf16 for tensor-core GEMM
__device__ __nv_bfloat16 g_h0[B_SZ * HID];

// ---------------------------------------------------------------------------
// Kernel 1: h0_last[b, h] for the 256 last-timestep tokens. (validated)
// ---------------------------------------------------------------------------
__global__ void __launch_bounds__(256) lstm_h0_kernel(
    const int* __restrict__ X, const float* __restrict__ C_table,
    const float* __restrict__ U_i, const float* __restrict__ b_i,
    const float* __restrict__ U_c, const float* __restrict__ b_c,
    const float* __restrict__ U_o, const float* __restrict__ b_o)
{
    __shared__ float E_s[8][EMB];
    const int tid = threadIdx.x;
    const int b0  = blockIdx.y * 8;

    for (int i = tid; i < 8 * EMB; i += 256) {
        int b = i >> 7;
        int e = i & (EMB - 1);
        int tok = X[(b0 + b) * T_SZ + (T_SZ - 1)];
        E_s[b][e] = C_table[tok * EMB + e];
    }
    __syncthreads();

    const int h    = blockIdx.x * 64 + (tid & 63);
    const int bsub = tid >> 6;
    const int r0   = bsub * 2;

    float ai[2], ag[2], ao[2];
    const float bi = b_i[h], bc = b_c[h], bo = b_o[h];
#pragma unroll
    for (int r = 0; r < 2; r++) { ai[r] = bi; ag[r] = bc; ao[r] = bo; }

#pragma unroll 4
    for (int e = 0; e < EMB; e++) {
        float ui = U_i[e * HID + h];
        float uc = U_c[e * HID + h];
        float uo = U_o[e * HID + h];
#pragma unroll
        for (int r = 0; r < 2; r++) {
            float ev = E_s[r0 + r][e];
            ai[r] = fmaf(ev, ui, ai[r]);
            ag[r] = fmaf(ev, uc, ag[r]);
            ao[r] = fmaf(ev, uo, ao[r]);
        }
    }

#pragma unroll
    for (int r = 0; r < 2; r++) {
        float i0 = 1.0f / (1.0f + __expf(-ai[r]));
        float g0 = tanhf(ag[r]);
        float o0 = 1.0f / (1.0f + __expf(-ao[r]));
        float c0 = i0 * g0;
        float h0 = o0 * tanhf(c0);
        g_h0[(b0 + r0 + r) * HID + h] = __float2bfloat16(h0);
    }
}

// ---------------------------------------------------------------------------
// Kernel 2: logits[256, 32000] = h0[256,256] @ W_w[32000,256]^T + b_out
// bf16 mma.sync GEMM with B STREAMED DIRECTLY FROM GLOBAL (no B smem, no
// cp.async, no chunk barriers).
//   CTA tile: M=256 x N=128, K=256. grid = (250,1), 512 threads.
//   A (all of h0, bf16) in smem, fragments via ldmatrix.x4 (validated).
//   B fragments: per warp per kk, 8x LDG.64 fp32 (sector-coalesced:
//   each n-row contributes one full 32B sector), cvt to bf16 at use.
//   ONE __syncthreads total; 16-kk loop is straight-line -> deep LDG MLP.
// ---------------------------------------------------------------------------
#define BM      256
#define BN      128
#define ASTR    264              // A_s row stride in bf16 (528B = 33*16)

__global__ void __launch_bounds__(512, 1) logits_kernel(
    const float* __restrict__ W_w, const float* __restrict__ b_out,
    float* __restrict__ out)
{
    extern __shared__ char smem_raw[];
    __nv_bfloat16* A_s = (__nv_bfloat16*)smem_raw;   // [256][ASTR]

    const int tid = threadIdx.x;
    const int n0  = blockIdx.x * BN;

    // --- load A: all of g_h0 (128KB), LDG.128 -> STS.128, one sync ---
    {
        const uint4* src = (const uint4*)g_h0;
#pragma unroll
        for (int k = 0; k < 16; k++) {
            int idx = tid + k * 512;       // 8192 segs (256 rows x 32 segs)
            int row = idx >> 5;
            int seg = idx & 31;
            uint4 v = src[row * 32 + seg];
            *(uint4*)((char*)A_s + row * (ASTR * 2) + seg * 16) = v;
        }
    }
    __syncthreads();

    const int wid  = tid >> 5;
    const int lane = tid & 31;
    const int wm   = wid >> 2;      // 0..3 -> M offset wm*64
    const int wn   = wid & 3;       // 0..3 -> N offset wn*32
    const int gr   = lane >> 2;
    const int tig  = lane & 3;
    // ldmatrix lane address components (validated R5/R6):
    const int lm_row = (lane & 15);
    const int lm_col = ((lane >> 4) & 1) << 3;

    // Per-thread B base pointers: row n0+wn*32+ni*8+gr, col offset tig*2.
    const float* bp[4];
#pragma unroll
    for (int ni = 0; ni < 4; ni++)
        bp[ni] = W_w + (size_t)(n0 + wn * 32 + ni * 8 + gr) * HID + tig * 2;

    float acc[4][4][4];
#pragma unroll
    for (int mi = 0; mi < 4; mi++)
#pragma unroll
        for (int ni = 0; ni < 4; ni++)
#pragma unroll
            for (int r = 0; r < 4; r++) acc[mi][ni][r] = 0.0f;

#pragma unroll
    for (int kk = 0; kk < HID / 16; kk++) {
        const int kb = kk * 16;

        // B fragments straight from global: 8x LDG.64 fp32, cvt to bf16
        uint32_t bf[4][2];
#pragma unroll
        for (int ni = 0; ni < 4; ni++) {
            float2 f0 = *(const float2*)(bp[ni] + kb);      // k = kb+tig*2,+1
            float2 f1 = *(const float2*)(bp[ni] + kb + 8);  // k = kb+8+tig*2,+1
            __nv_bfloat162 p0 = __floats2bfloat162_rn(f0.x, f0.y);
            __nv_bfloat162 p1 = __floats2bfloat162_rn(f1.x, f1.y);
            bf[ni][0] = *(const uint32_t*)&p0;
            bf[ni][1] = *(const uint32_t*)&p1;
        }

        // A fragments from smem via ldmatrix.x4
        uint32_t a[4][4];
#pragma unroll
        for (int mi = 0; mi < 4; mi++) {
            uint32_t addr = (uint32_t)__cvta_generic_to_shared(
                &A_s[(wm * 64 + mi * 16 + lm_row) * ASTR + kb + lm_col]);
            asm volatile(
                "ldmatrix.sync.aligned.m8n8.x4.shared.b16 {%0,%1,%2,%3}, [%4];"
                : "=r"(a[mi][0]), "=r"(a[mi][1]), "=r"(a[mi][2]), "=r"(a[mi][3])
                : "r"(addr));
        }

#pragma unroll
        for (int mi = 0; mi < 4; mi++) {
#pragma unroll
            for (int ni = 0; ni < 4; ni++) {
                asm volatile(
                    "mma.sync.aligned.m16n8k16.row.col.f32.bf16.bf16.f32 "
                    "{%0,%1,%2,%3}, {%4,%5,%6,%7}, {%8,%9}, {%0,%1,%2,%3};"
                    : "+f"(acc[mi][ni][0]), "+f"(acc[mi][ni][1]),
                      "+f"(acc[mi][ni][2]), "+f"(acc[mi][ni][3])
                    : "r"(a[mi][0]), "r"(a[mi][1]), "r"(a[mi][2]), "r"(a[mi][3]),
                      "r"(bf[ni][0]), "r"(bf[ni][1]));
            }
        }
    }

    // ---- epilogue: add b_out, fp32 float2 stores (validated) ----
    float bo0[4], bo1[4];
#pragma unroll
    for (int ni = 0; ni < 4; ni++) {
        int col = n0 + wn * 32 + ni * 8 + tig * 2;
        bo0[ni] = b_out[col];
        bo1[ni] = b_out[col + 1];
    }
#pragma unroll
    for (int mi = 0; mi < 4; mi++) {
        int row = wm * 64 + mi * 16 + gr;
#pragma unroll
        for (int ni = 0; ni < 4; ni++) {
            int col = n0 + wn * 32 + ni * 8 + tig * 2;
            float2 v0 = make_float2(acc[mi][ni][0] + bo0[ni],
                                    acc[mi][ni][1] + bo1[ni]);
            float2 v1 = make_float2(acc[mi][ni][2] + bo0[ni],
                                    acc[mi][ni][3] + bo1[ni]);
            *(float2*)(&out[(size_t)row * NCLS + col])       = v0;
            *(float2*)(&out[(size_t)(row + 8) * NCLS + col]) = v1;
        }
    }
}

// ---------------------------------------------------------------------------
// Launcher
// Input order: 0=X 1=C_table 2=U_i 3=V_i 4=b_i 5=U_f 6=V_f 7=b_f
//  8=U_c 9=V_c 10=b_c 11=U_o 12=V_o 13=b_o 14..25=layer1 (unused) 26=W_w 27=b_out
// ---------------------------------------------------------------------------
extern "C" void kernel_launch(void* const* d_in, const int* in_sizes, int n_in,
                              void* d_out, int out_size)
{
    const int*   X       = (const int*)d_in[0];
    const float* C_table = (const float*)d_in[1];
    const float* U_i     = (const float*)d_in[2];
    const float* b_i     = (const float*)d_in[4];
    const float* U_c     = (const float*)d_in[8];
    const float* b_c     = (const float*)d_in[10];
    const float* U_o     = (const float*)d_in[11];
    const float* b_o     = (const float*)d_in[13];
    const float* W_w     = (const float*)d_in[26];
    const float* b_out   = (const float*)d_in[27];
    float* out = (float*)d_out;

    dim3 grid1(4, 32);
    lstm_h0_kernel<<<grid1, 256>>>(X, C_table, U_i, b_i, U_c, b_c, U_o, b_o);

    const int smem_bytes = BM * ASTR * 2;   // 135168
    cudaFuncSetAttribute(logits_kernel,
                         cudaFuncAttributeMaxDynamicSharedMemorySize, smem_bytes);
    logits_kernel<<<NCLS / BN, 512, smem_bytes>>>(W_w, b_out, out);
}